// round 15
// baseline (speedup 1.0000x reference)
#include <cuda_runtime.h>
#include <cuda_bf16.h>
#include <cstdint>

#define HW   1024
#define CD   128
#define EPSF 1e-8f
#define STAGE_B 32768   // kc=32 stage: A_hi 8K|A_lo 8K|B_hi 8K|B_lo 8K (M=N=128)

// Normalized features, bf16 hi/lo split, pixel-major:
// g_feat[view][p][0..127]=hi, [128..255]=lo   (512 B per pixel row)
__device__ __nv_bfloat16 g_feat[32 * HW * 256];

// ---------------------------------------------------------------------------
__device__ __forceinline__ uint32_t smem_u32(const void* p) {
    uint32_t a;
    asm("{ .reg .u64 t; cvta.to.shared.u64 t, %1; cvt.u32.u64 %0, t; }" : "=r"(a) : "l"(p));
    return a;
}

#define CP_ASYNC(s, g) \
    asm volatile("cp.async.cg.shared.global [%0], [%1], 16;" :: "r"(s), "l"(g))
#define CP_COMMIT() asm volatile("cp.async.commit_group;" ::: "memory")
#define CP_WAIT0()  asm volatile("cp.async.wait_group 0;" ::: "memory")

#define LDSM4(r, a) \
    asm volatile("ldmatrix.sync.aligned.m8n8.x4.shared.b16 {%0,%1,%2,%3}, [%4];" \
        : "=r"((r)[0]), "=r"((r)[1]), "=r"((r)[2]), "=r"((r)[3]) : "r"(a))

#define MMA(d, a, b0v, b1v)                                                  \
    asm volatile(                                                            \
        "mma.sync.aligned.m16n8k16.row.col.f32.bf16.bf16.f32 "               \
        "{%0,%1,%2,%3}, {%4,%5,%6,%7}, {%8,%9}, {%0,%1,%2,%3};\n"            \
        : "+f"((d)[0]), "+f"((d)[1]), "+f"((d)[2]), "+f"((d)[3])             \
        : "r"((a)[0]), "r"((a)[1]), "r"((a)[2]), "r"((a)[3]),                \
          "r"(b0v), "r"(b1v))

// ---------------------------------------------------------------------------
// Kernel 1: L2-normalize per pixel, split to bf16 hi/lo, write pixel-major.
// 256 blocks x 128 threads (covers all SMs).
// ---------------------------------------------------------------------------
__global__ __launch_bounds__(128) void norm_split_kernel(const float* __restrict__ x) {
    __shared__ uint32_t tile[4][33 * 32];
    int w = threadIdx.x >> 5, l = threadIdx.x & 31;
    int gp = blockIdx.x * 128 + w * 32 + l;        // global pixel over 32 views
    int view = gp >> 10, p = gp & 1023;
    const float* xp = x + (size_t)view * (CD * HW) + p;

    float s = 0.f;
#pragma unroll 8
    for (int c = 0; c < CD; ++c) { float v = xp[c << 10]; s += v * v; }
    float inv = 1.f / (sqrtf(s) + EPSF);

    __nv_bfloat16* ob = g_feat + (size_t)(gp - l) * 256;   // warp's base pixel row

    for (int cb = 0; cb < 4; ++cb) {
#pragma unroll
        for (int ci = 0; ci < 32; ++ci) {
            float v = xp[(cb * 32 + ci) << 10] * inv;
            __nv_bfloat16 h = __float2bfloat16(v);
            __nv_bfloat16 lo = __float2bfloat16(v - __bfloat162float(h));
            tile[w][ci * 33 + l] = (uint32_t)__bfloat16_as_ushort(h)
                                 | ((uint32_t)__bfloat16_as_ushort(lo) << 16);
        }
        __syncwarp();
#pragma unroll
        for (int rr = 0; rr < 32; ++rr) {
            uint32_t v = tile[w][l * 33 + rr];
            __nv_bfloat16* row = ob + (size_t)rr * 256 + cb * 32 + l;
            row[0]   = __ushort_as_bfloat16((unsigned short)(v & 0xFFFF));
            row[128] = __ushort_as_bfloat16((unsigned short)(v >> 16));
        }
        __syncwarp();
    }
}

// ---------------------------------------------------------------------------
// Kernel 2: HMMA GEMM over the 48 unique view pairs; CTA tile 128x128
// (8 warps 2x4, warp 64x32 = R10's proven warp shape), kc=32, 2-stage
// cp.async, ONE sync per chunk. Each CTA writes G direct to out[idx1] and
// transposed (per-warp swizzled smem aliasing the dead stages) to out[idx2].
// 128x128 tile => 33% less L2 load traffic than 128x64.
// smem 64KB, 3 CTAs/SM (24 warps).
// ---------------------------------------------------------------------------
__constant__ int c_pi[6] = {0, 0, 0, 1, 1, 2};
__constant__ int c_pj[6] = {1, 2, 3, 2, 3, 3};

__global__ __launch_bounds__(256, 3) void corr_gemm10(float* __restrict__ out) {
    extern __shared__ char smem[];
    uint32_t sb = smem_u32(smem);
    const int tid = threadIdx.x;
    const int w = tid >> 5, l = tid & 31;
    const int wm = w >> 2, wn = w & 3;          // warp grid 2x4
    const int lo16 = l & 15, hi2 = l >> 4;
    const int g = l >> 2, tg = l & 3;

    const int q0 = blockIdx.x * 128;
    const int p0 = blockIdx.y * 128;
    const int z  = blockIdx.z;                  // 0..47
    const int b  = z / 6, u = z % 6;
    const int i  = c_pi[u], j = c_pj[u];
    const int idx1 = b * 12 + i * 3 + (j - 1);  // A=f_j rows, B=f_i cols
    const int idx2 = b * 12 + j * 3 + i;        // transposed twin

    const char* Af = (const char*)g_feat + (size_t)(b * 4 + j) * HW * 512 + (size_t)p0 * 512;
    const char* Bf = (const char*)g_feat + (size_t)(b * 4 + i) * HW * 512 + (size_t)q0 * 512;

    float acc[4][4][4];
#pragma unroll
    for (int mt = 0; mt < 4; ++mt)
#pragma unroll
        for (int nt = 0; nt < 4; ++nt)
#pragma unroll
            for (int e = 0; e < 4; ++e) acc[mt][nt][e] = 0.f;

    // ---- stage loader: 2048 16B chunks (A+B, hi+lo), 8 per thread ----
    auto load_stage = [&](int kc) {
        uint32_t sbase = sb + (uint32_t)(kc & 1) * STAGE_B;
        const char* As = Af + kc * 64;
        const char* Bs = Bf + kc * 64;
#pragma unroll
        for (int it = 0; it < 4; ++it) {
            int c = it * 256 + tid;
            int m = c >> 3, half = (c >> 2) & 1, ch = c & 3;
            uint32_t soff = half * 8192u + (uint32_t)((m * 4 + (ch ^ ((m >> 1) & 3))) << 4);
            size_t goff = (size_t)m * 512 + half * 256 + ch * 16;
            CP_ASYNC(sbase + soff,         As + goff);
            CP_ASYNC(sbase + 16384 + soff, Bs + goff);
        }
    };

    load_stage(0);
    CP_COMMIT();

    for (int kc = 0; kc < 4; ++kc) {
        CP_WAIT0();
        __syncthreads();            // stage kc visible; stage kc-1 fully read
        if (kc < 3) { load_stage(kc + 1); CP_COMMIT(); }

        uint32_t st = sb + (uint32_t)(kc & 1) * STAGE_B;

#pragma unroll
        for (int ks = 0; ks < 2; ++ks) {         // k offsets 0, 16 within chunk
            const int ch = ks * 2 + hi2;         // lane's 16B chunk (0..3)

            uint32_t ah[4][4], al[4][4], bb[2][4], swb[2];
#pragma unroll
            for (int mt = 0; mt < 4; ++mt) {
                int m = wm * 64 + mt * 16 + lo16;
                uint32_t sw = (uint32_t)((m * 4 + (ch ^ ((m >> 1) & 3))) << 4);
                LDSM4(ah[mt], st + sw);
                LDSM4(al[mt], st + 8192 + sw);
            }
#pragma unroll
            for (int np = 0; np < 2; ++np) {
                int n = wn * 32 + np * 16 + lo16;
                swb[np] = (uint32_t)((n * 4 + (ch ^ ((n >> 1) & 3))) << 4);
                LDSM4(bb[np], st + 16384 + swb[np]);   // B_hi
            }
#pragma unroll
            for (int mt = 0; mt < 4; ++mt)
#pragma unroll
                for (int nt = 0; nt < 4; ++nt)
                    MMA(acc[mt][nt], ah[mt], bb[nt >> 1][nt & 1], bb[nt >> 1][2 + (nt & 1)]);
#pragma unroll
            for (int mt = 0; mt < 4; ++mt)
#pragma unroll
                for (int nt = 0; nt < 4; ++nt)
                    MMA(acc[mt][nt], al[mt], bb[nt >> 1][nt & 1], bb[nt >> 1][2 + (nt & 1)]);
#pragma unroll
            for (int np = 0; np < 2; ++np)
                LDSM4(bb[np], st + 24576 + swb[np]);   // B_lo
#pragma unroll
            for (int mt = 0; mt < 4; ++mt)
#pragma unroll
                for (int nt = 0; nt < 4; ++nt)
                    MMA(acc[mt][nt], ah[mt], bb[nt >> 1][nt & 1], bb[nt >> 1][2 + (nt & 1)]);
        }
        // (no bottom sync: next iteration's top sync orders stage reuse)
    }

    const int gl = l >> 2;

    // ---- epilogue 1: direct fp32 float2 stores to out[idx1] ----
    {
        float* op = out + (size_t)idx1 * (HW * HW);
#pragma unroll
        for (int mt = 0; mt < 4; ++mt) {
#pragma unroll
            for (int nt = 0; nt < 4; ++nt) {
                int row = p0 + wm * 64 + mt * 16 + gl;
                int col = q0 + wn * 32 + nt * 8 + tg * 2;
                *(float2*)&op[(size_t)row * HW + col] =
                    make_float2(acc[mt][nt][0], acc[mt][nt][1]);
                *(float2*)&op[(size_t)(row + 8) * HW + col] =
                    make_float2(acc[mt][nt][2], acc[mt][nt][3]);
            }
        }
    }

    // ---- epilogue 2: transposed tile to out[idx2] via swizzled smem ----
    __syncthreads();                // tw aliases the dead stage buffers
    {
        float* tw = (float*)smem + w * 2048;   // per-warp 8KB: G[n][m], n<32, m<64
#pragma unroll
        for (int mt = 0; mt < 4; ++mt)
#pragma unroll
            for (int nt = 0; nt < 4; ++nt)
#pragma unroll
                for (int e = 0; e < 4; ++e) {
                    int n = nt * 8 + tg * 2 + (e & 1);
                    int m = mt * 16 + g + 8 * (e >> 1);
                    tw[n * 64 + (m ^ ((n & 6) << 2))] = acc[mt][nt][e];
                }
        __syncwarp();

        float* op = out + (size_t)idx2 * (HW * HW);
        const float2* tw2 = (const float2*)tw;
#pragma unroll
        for (int n = 0; n < 32; ++n) {
            float2 v = tw2[n * 32 + (l ^ ((n & 6) << 1))];   // (G[n][2l], G[n][2l+1])
            *(float2*)&op[(size_t)(q0 + wn * 32 + n) * HW + p0 + wm * 64 + 2 * l] = v;
        }
    }
}

// ---------------------------------------------------------------------------
extern "C" void kernel_launch(void* const* d_in, const int* in_sizes, int n_in,
                              void* d_out, int out_size) {
    const float* x = (const float*)d_in[0];
    float* out = (float*)d_out;

    norm_split_kernel<<<256, 128>>>(x);

    cudaFuncSetAttribute(corr_gemm10, cudaFuncAttributeMaxDynamicSharedMemorySize, 2 * STAGE_B);
    dim3 grid(8, 8, 48);
    corr_gemm10<<<grid, 256, 2 * STAGE_B>>>(out);
}

// round 16
// speedup vs baseline: 2.1114x; 2.1114x over previous
#include <cuda_runtime.h>
#include <cuda_bf16.h>
#include <cstdint>

#define HW   1024
#define CD   128
#define EPSF 1e-8f
#define STAGE_B 24576   // A(16KB) + B(8KB) per kc=32 stage

// Normalized features, bf16 hi/lo split, pixel-major:
// g_feat[view][p][0..127]=hi, [128..255]=lo   (512 B per pixel row)
__device__ __nv_bfloat16 g_feat[32 * HW * 256];

// ---------------------------------------------------------------------------
__device__ __forceinline__ uint32_t smem_u32(const void* p) {
    uint32_t a;
    asm("{ .reg .u64 t; cvta.to.shared.u64 t, %1; cvt.u32.u64 %0, t; }" : "=r"(a) : "l"(p));
    return a;
}

#define CP_ASYNC(s, g) \
    asm volatile("cp.async.cg.shared.global [%0], [%1], 16;" :: "r"(s), "l"(g))
#define CP_COMMIT() asm volatile("cp.async.commit_group;" ::: "memory")
#define CP_WAIT0()  asm volatile("cp.async.wait_group 0;" ::: "memory")

#define LDSM4(r, a) \
    asm volatile("ldmatrix.sync.aligned.m8n8.x4.shared.b16 {%0,%1,%2,%3}, [%4];" \
        : "=r"((r)[0]), "=r"((r)[1]), "=r"((r)[2]), "=r"((r)[3]) : "r"(a))

#define MMA(d, a, b0v, b1v)                                                  \
    asm volatile(                                                            \
        "mma.sync.aligned.m16n8k16.row.col.f32.bf16.bf16.f32 "               \
        "{%0,%1,%2,%3}, {%4,%5,%6,%7}, {%8,%9}, {%0,%1,%2,%3};\n"            \
        : "+f"((d)[0]), "+f"((d)[1]), "+f"((d)[2]), "+f"((d)[3])             \
        : "r"((a)[0]), "r"((a)[1]), "r"((a)[2]), "r"((a)[3]),                \
          "r"(b0v), "r"(b1v))

// ---------------------------------------------------------------------------
// Kernel 1 (v2): L2-normalize per pixel + bf16 hi/lo split, pixel-major out.
// 4 threads per pixel (one per 32-channel quarter); shfl reduction for the
// norm; second pass re-reads from L1; vector (16B) stores. 512x256 grid.
// ---------------------------------------------------------------------------
__global__ __launch_bounds__(256) void norm_split_kernel2(const float* __restrict__ x) {
    int t = blockIdx.x * 256 + threadIdx.x;      // 0..131071
    int gp = t >> 2;                             // pixel over all views
    int qt = t & 3;                              // channel quarter 0..3
    int view = gp >> 10, p = gp & 1023;

    const float* xp = x + (size_t)view * (CD * HW) + (size_t)(qt * 32) * HW + p;

    float v[32];
    float s = 0.f;
#pragma unroll
    for (int c = 0; c < 32; ++c) {
        v[c] = xp[c << 10];
        s += v[c] * v[c];
    }
    // reduce across the 4 lanes of this pixel
    s += __shfl_xor_sync(0xFFFFFFFFu, s, 1);
    s += __shfl_xor_sync(0xFFFFFFFFu, s, 2);
    float inv = 1.f / (sqrtf(s) + EPSF);

    // write hi quarter (64B) + lo quarter (64B) as 4+4 16B stores
    __nv_bfloat16* row = g_feat + (size_t)gp * 256 + qt * 32;
    ushort hi[32], lo[32];
#pragma unroll
    for (int c = 0; c < 32; ++c) {
        float f = v[c] * inv;
        __nv_bfloat16 h = __float2bfloat16(f);
        hi[c] = __bfloat16_as_ushort(h);
        lo[c] = __bfloat16_as_ushort(__float2bfloat16(f - __bfloat162float(h)));
    }
#pragma unroll
    for (int c8 = 0; c8 < 4; ++c8) {
        uint4 vh, vl;
        vh.x = (uint32_t)hi[c8*8+0] | ((uint32_t)hi[c8*8+1] << 16);
        vh.y = (uint32_t)hi[c8*8+2] | ((uint32_t)hi[c8*8+3] << 16);
        vh.z = (uint32_t)hi[c8*8+4] | ((uint32_t)hi[c8*8+5] << 16);
        vh.w = (uint32_t)hi[c8*8+6] | ((uint32_t)hi[c8*8+7] << 16);
        vl.x = (uint32_t)lo[c8*8+0] | ((uint32_t)lo[c8*8+1] << 16);
        vl.y = (uint32_t)lo[c8*8+2] | ((uint32_t)lo[c8*8+3] << 16);
        vl.z = (uint32_t)lo[c8*8+4] | ((uint32_t)lo[c8*8+5] << 16);
        vl.w = (uint32_t)lo[c8*8+6] | ((uint32_t)lo[c8*8+7] << 16);
        *(uint4*)(row + c8 * 8)       = vh;
        *(uint4*)(row + 128 + c8 * 8) = vl;
    }
}

// ---------------------------------------------------------------------------
// Kernel 2 (R10 champion, verbatim): HMMA GEMM over 48 unique view pairs;
// CTA tile 128x64 (4 warps, warp 64x32), kc=32, 2-stage cp.async, one sync
// per chunk. Direct stores to out[idx1]; transposed twin to out[idx2] via
// per-warp swizzled smem. smem 48KB -> 4 CTAs/SM.
// ---------------------------------------------------------------------------
__constant__ int c_pi[6] = {0, 0, 0, 1, 1, 2};
__constant__ int c_pj[6] = {1, 2, 3, 2, 3, 3};

__global__ __launch_bounds__(128, 4) void corr_gemm6(float* __restrict__ out) {
    extern __shared__ char smem[];
    uint32_t sb = smem_u32(smem);
    const int tid = threadIdx.x;
    const int w = tid >> 5, l = tid & 31;
    const int wm = w >> 1, wn = w & 1;          // warp grid 2x2
    const int lo16 = l & 15, hi2 = l >> 4;
    const int g = l >> 2, tg = l & 3;

    const int q0 = blockIdx.x * 64;
    const int p0 = blockIdx.y * 128;
    const int z  = blockIdx.z;                  // 0..47
    const int b  = z / 6, u = z % 6;
    const int i  = c_pi[u], j = c_pj[u];
    const int idx1 = b * 12 + i * 3 + (j - 1);
    const int idx2 = b * 12 + j * 3 + i;

    const char* Af = (const char*)g_feat + (size_t)(b * 4 + j) * HW * 512 + (size_t)p0 * 512;
    const char* Bf = (const char*)g_feat + (size_t)(b * 4 + i) * HW * 512 + (size_t)q0 * 512;

    float acc[4][4][4];
#pragma unroll
    for (int mt = 0; mt < 4; ++mt)
#pragma unroll
        for (int nt = 0; nt < 4; ++nt)
#pragma unroll
            for (int e = 0; e < 4; ++e) acc[mt][nt][e] = 0.f;

    // ---- stage loader: 1536 16B chunks (A 1024 + B 512), 12 per thread ----
    auto load_stage = [&](int kc) {
        uint32_t sbase = sb + (uint32_t)(kc & 1) * STAGE_B;
        const char* Af2 = Af + kc * 64;
        const char* Bf2 = Bf + kc * 64;
#pragma unroll
        for (int it = 0; it < 12; ++it) {
            int c = it * 128 + tid;             // 0..1535
            if (c < 1024) {                     // A region (it 0..7)
                int m = c >> 3, half = (c >> 2) & 1, ch = c & 3;
                uint32_t soff = half * 8192u
                              + (uint32_t)((m * 4 + (ch ^ ((m >> 1) & 3))) << 4);
                CP_ASYNC(sbase + soff, Af2 + (size_t)m * 512 + half * 256 + ch * 16);
            } else {                            // B region (it 8..11)
                int u2 = c - 1024;
                int m = u2 >> 3, half = (u2 >> 2) & 1, ch = u2 & 3;
                uint32_t soff = 16384u + half * 4096u
                              + (uint32_t)((m * 4 + (ch ^ ((m >> 1) & 3))) << 4);
                CP_ASYNC(sbase + soff, Bf2 + (size_t)m * 512 + half * 256 + ch * 16);
            }
        }
    };

    load_stage(0);
    CP_COMMIT();

    for (int kc = 0; kc < 4; ++kc) {
        CP_WAIT0();
        __syncthreads();
        if (kc < 3) { load_stage(kc + 1); CP_COMMIT(); }

        uint32_t st = sb + (uint32_t)(kc & 1) * STAGE_B;
#pragma unroll
        for (int ks = 0; ks < 2; ++ks) {
            const int ch = ks * 2 + hi2;

            uint32_t ah[4][4], al[4][4], bb[2][4], swb[2];
#pragma unroll
            for (int mt = 0; mt < 4; ++mt) {
                int m = wm * 64 + mt * 16 + lo16;
                uint32_t sw = (uint32_t)((m * 4 + (ch ^ ((m >> 1) & 3))) << 4);
                LDSM4(ah[mt], st + sw);
                LDSM4(al[mt], st + 8192 + sw);
            }
#pragma unroll
            for (int np = 0; np < 2; ++np) {
                int n = wn * 32 + np * 16 + lo16;
                swb[np] = (uint32_t)((n * 4 + (ch ^ ((n >> 1) & 3))) << 4);
                LDSM4(bb[np], st + 16384 + swb[np]);  // B_hi
            }
#pragma unroll
            for (int mt = 0; mt < 4; ++mt)
#pragma unroll
                for (int nt = 0; nt < 4; ++nt)
                    MMA(acc[mt][nt], ah[mt], bb[nt >> 1][nt & 1], bb[nt >> 1][2 + (nt & 1)]);
#pragma unroll
            for (int mt = 0; mt < 4; ++mt)
#pragma unroll
                for (int nt = 0; nt < 4; ++nt)
                    MMA(acc[mt][nt], al[mt], bb[nt >> 1][nt & 1], bb[nt >> 1][2 + (nt & 1)]);
#pragma unroll
            for (int np = 0; np < 2; ++np)
                LDSM4(bb[np], st + 20480 + swb[np]);  // B_lo
#pragma unroll
            for (int mt = 0; mt < 4; ++mt)
#pragma unroll
                for (int nt = 0; nt < 4; ++nt)
                    MMA(acc[mt][nt], ah[mt], bb[nt >> 1][nt & 1], bb[nt >> 1][2 + (nt & 1)]);
        }
    }

    // ---- epilogue 1: direct fp32 float2 stores to out[idx1] ----
    {
        float* op = out + (size_t)idx1 * (HW * HW);
#pragma unroll
        for (int mt = 0; mt < 4; ++mt) {
#pragma unroll
            for (int nt = 0; nt < 4; ++nt) {
                int row = p0 + wm * 64 + mt * 16 + g;
                int col = q0 + wn * 32 + nt * 8 + tg * 2;
                *(float2*)&op[(size_t)row * HW + col] =
                    make_float2(acc[mt][nt][0], acc[mt][nt][1]);
                *(float2*)&op[(size_t)(row + 8) * HW + col] =
                    make_float2(acc[mt][nt][2], acc[mt][nt][3]);
            }
        }
    }

    // ---- epilogue 2: transposed tile to out[idx2] via swizzled smem ----
    __syncthreads();
    {
        float* tw = (float*)smem + w * 2048;   // per-warp 8KB: G[n][m], n<32, m<64
#pragma unroll
        for (int mt = 0; mt < 4; ++mt)
#pragma unroll
            for (int nt = 0; nt < 4; ++nt)
#pragma unroll
                for (int e = 0; e < 4; ++e) {
                    int n = nt * 8 + tg * 2 + (e & 1);
                    int m = mt * 16 + g + 8 * (e >> 1);
                    tw[n * 64 + (m ^ ((n & 6) << 2))] = acc[mt][nt][e];
                }
        __syncwarp();

        float* op = out + (size_t)idx2 * (HW * HW);
        const float2* tw2 = (const float2*)tw;
#pragma unroll
        for (int n = 0; n < 32; ++n) {
            float2 v = tw2[n * 32 + (l ^ ((n & 6) << 1))];   // (G[n][2l], G[n][2l+1])
            *(float2*)&op[(size_t)(q0 + wn * 32 + n) * HW + p0 + wm * 64 + 2 * l] = v;
        }
    }
}

// ---------------------------------------------------------------------------
extern "C" void kernel_launch(void* const* d_in, const int* in_sizes, int n_in,
                              void* d_out, int out_size) {
    const float* x = (const float*)d_in[0];
    float* out = (float*)d_out;

    norm_split_kernel2<<<512, 256>>>(x);

    int smem_sz = 2 * STAGE_B;   // 48 KB
    cudaFuncSetAttribute(corr_gemm6, cudaFuncAttributeMaxDynamicSharedMemorySize, smem_sz);
    dim3 grid(16, 8, 48);
    corr_gemm6<<<grid, 128, smem_sz>>>(out);
}